// round 6
// baseline (speedup 1.0000x reference)
#include <cuda_runtime.h>
#include <cstdint>

// ============================================================
// SVDDecomposeTransMatrix — fused persistent kernel.
//   Blocks 0-3: Cayley (Horner product) + compose -> g_ML/g_MR, release flag.
//   Blocks 4+ : prefetch x into L2 while waiting, then all blocks run the
//               batched 64x64 Kronecker GEMM (TF32 mma) off a dynamic queue.
//   Queue index is per-BLOCK: leader atomicAdd + smem broadcast.
// ============================================================

#define MSTR 68   // prep smem stride
#define SSTR 72   // kron smem stride (conflict-free fragment reads)
#define NBLK 304  // 152 SMs * 2 (all resident in wave 1 -> spin is safe)

__device__ float g_Qv[2][4096];   // Cayley(v_left), Cayley(v_right)
__device__ float g_ML[4096];      // TRANSPOSED m_left
__device__ float g_MR[4096];      // m_right row-major
__device__ int g_qdone[2];
__device__ int g_mdone;
__device__ unsigned g_work;

__global__ void reset_kernel() {
    g_qdone[0] = 0; g_qdone[1] = 0; g_mdone = 0; g_work = 0;
}

__device__ __forceinline__ int ld_acquire(const int* p) {
    int v;
    asm volatile("ld.acquire.gpu.b32 %0, [%1];" : "=r"(v) : "l"(p));
    return v;
}
__device__ __forceinline__ int ld_relaxed(const int* p) {
    int v;
    asm volatile("ld.relaxed.gpu.b32 %0, [%1];" : "=r"(v) : "l"(p));
    return v;
}

// C = A*B (+Sadd), 64x64 stride MSTR, 256 threads, 2x8 tiles.
template <bool FUSED_ADD>
__device__ __forceinline__ void mm256(const float* __restrict__ A,
                                      const float* __restrict__ B,
                                      const float* __restrict__ Sadd,
                                      float* __restrict__ C, int tid) {
    int r0 = (tid >> 3) * 2;
    int c0 = (tid & 7) * 8;
    float a0[8] = {0,0,0,0,0,0,0,0};
    float a1[8] = {0,0,0,0,0,0,0,0};
#pragma unroll 8
    for (int k = 0; k < 64; ++k) {
        float4 bl = *(const float4*)&B[k * MSTR + c0];
        float4 bh = *(const float4*)&B[k * MSTR + c0 + 4];
        float x0 = A[r0 * MSTR + k];
        float x1 = A[(r0 + 1) * MSTR + k];
        a0[0]+=x0*bl.x; a0[1]+=x0*bl.y; a0[2]+=x0*bl.z; a0[3]+=x0*bl.w;
        a0[4]+=x0*bh.x; a0[5]+=x0*bh.y; a0[6]+=x0*bh.z; a0[7]+=x0*bh.w;
        a1[0]+=x1*bl.x; a1[1]+=x1*bl.y; a1[2]+=x1*bl.z; a1[3]+=x1*bl.w;
        a1[4]+=x1*bh.x; a1[5]+=x1*bh.y; a1[6]+=x1*bh.z; a1[7]+=x1*bh.w;
    }
    if (FUSED_ADD) {
#pragma unroll
        for (int j = 0; j < 8; ++j) {
            a0[j] += Sadd[r0 * MSTR + c0 + j];
            a1[j] += Sadd[(r0 + 1) * MSTR + c0 + j];
        }
    }
    *(float4*)&C[r0 * MSTR + c0]           = make_float4(a0[0],a0[1],a0[2],a0[3]);
    *(float4*)&C[r0 * MSTR + c0 + 4]       = make_float4(a0[4],a0[5],a0[6],a0[7]);
    *(float4*)&C[(r0 + 1) * MSTR + c0]     = make_float4(a1[0],a1[1],a1[2],a1[3]);
    *(float4*)&C[(r0 + 1) * MSTR + c0 + 4] = make_float4(a1[4],a1[5],a1[6],a1[7]);
}

__device__ __forceinline__ unsigned f2tf(float f) {
    unsigned u;
    asm("cvt.rna.tf32.f32 %0, %1;" : "=r"(u) : "f"(f));
    return u;
}

__device__ __forceinline__ void mma_tf32(float& d0, float& d1, float& d2, float& d3,
                                         unsigned a0, unsigned a1, unsigned a2, unsigned a3,
                                         unsigned b0, unsigned b1) {
    asm volatile(
        "mma.sync.aligned.m16n8k8.row.col.f32.tf32.tf32.f32 "
        "{%0,%1,%2,%3}, {%4,%5,%6,%7}, {%8,%9}, {%0,%1,%2,%3};\n"
        : "+f"(d0), "+f"(d1), "+f"(d2), "+f"(d3)
        : "r"(a0), "r"(a1), "r"(a2), "r"(a3), "r"(b0), "r"(b1));
}

__global__ __launch_bounds__(256, 2)
void fused_kernel(const float* __restrict__ x,
                  const float* __restrict__ u_left,
                  const float* __restrict__ v_left,
                  const float* __restrict__ diag_left,
                  const float* __restrict__ u_right,
                  const float* __restrict__ v_right,
                  const float* __restrict__ diag_right,
                  const float* __restrict__ diag_scale,
                  float* __restrict__ out, int ntiles) {
    extern __shared__ float sm[];
    __shared__ unsigned sp;               // block-uniform queue index broadcast
    int tid = threadIdx.x;
    int bid = blockIdx.x;

    // ================= PHASE 1: prep (blocks 0-3) / prefetch (others) =========
    if (bid < 4) {
        // Cayley: Q = (I+B)(I+B)(I+B^2)(I+B^4)(I+B^8), B = A/2  (k<16 series)
        float* b0 = sm;
        float* b1 = b0 + 64 * MSTR;
        float* r0b = b1 + 64 * MSTR;
        float* r1b = r0b + 64 * MSTR;
        const float* X = (bid == 0) ? u_left : (bid == 1) ? v_left :
                         (bid == 2) ? u_right : v_right;
        for (int idx = tid; idx < 4096; idx += 256) {
            int i = idx >> 6, j = idx & 63;
            float a = (i > j) ? X[i * 64 + j] : (i < j ? -X[j * 64 + i] : 0.f);
            float b = 0.5f * a;
            b0[i * MSTR + j]  = b;
            r0b[i * MSTR + j] = (i == j) ? 1.f + b : b;
        }
        __syncthreads();
        mm256<true >(b0, r0b, r0b, r1b, tid);   // R <- (I+B)R
        mm256<false>(b0, b0, nullptr, b1, tid); // P <- B^2
        __syncthreads();
        mm256<true >(b1, r1b, r1b, r0b, tid);   // R <- (I+B^2)R
        mm256<false>(b1, b1, nullptr, b0, tid); // P <- B^4
        __syncthreads();
        mm256<true >(b0, r0b, r0b, r1b, tid);   // R <- (I+B^4)R
        mm256<false>(b0, b0, nullptr, b1, tid); // P <- B^8
        __syncthreads();
        mm256<true >(b1, r1b, r1b, r0b, tid);   // R <- (I+B^8)R  == Q (in r0b)
        __syncthreads();

        if (bid == 1 || bid == 3) {
            float* dst = g_Qv[bid >> 1];
            for (int idx = tid; idx < 4096; idx += 256) {
                int i = idx >> 6, j = idx & 63;
                dst[idx] = r0b[i * MSTR + j];
            }
            __threadfence();
            __syncthreads();
            if (tid == 0) atomicExch(&g_qdone[bid >> 1], 1);
        } else {
            // compose: M = Q_u @ diag(d) @ Q_v
            if (tid == 0) { while (ld_acquire(&g_qdone[bid >> 1]) == 0) __nanosleep(64); }
            __syncthreads();
            const float* Qv = g_Qv[bid >> 1];
            const float* d  = (bid == 0) ? diag_left : diag_right;
            for (int idx = tid; idx < 4096; idx += 256) {
                int i = idx >> 6, j = idx & 63;
                b0[i * MSTR + j] = d[i] * Qv[idx];
            }
            __syncthreads();
            mm256<false>(r0b, b0, nullptr, b1, tid);
            __syncthreads();
            for (int idx = tid; idx < 4096; idx += 256) {
                int a = idx >> 6, b = idx & 63;
                float v = b1[a * MSTR + b];
                if (bid == 0) g_ML[b * 64 + a] = v;   // m_left transposed
                else          g_MR[a * 64 + b] = v;
            }
            __threadfence();
            __syncthreads();
            if (tid == 0) atomicAdd(&g_mdone, 1);
        }
    } else {
        // prefetch x into L2 while prep runs
        const char* xb = (const char*)x;
        for (int q = bid; q < ntiles; q += gridDim.x) {
            if (ld_relaxed(&g_mdone) >= 2) break;
            if (tid < 128) {
                const char* p = xb + (size_t)q * 16384 + tid * 128;
                asm volatile("prefetch.global.L2 [%0];" :: "l"(p));
            }
        }
    }

    // ================= barrier on prep completion =================
    if (tid == 0) { while (ld_acquire(&g_mdone) < 2) __nanosleep(32); }
    __syncthreads();

    // ================= PHASE 2: kron GEMMs, 2 tiles per iteration =========
    float* sDiag = sm;                       // 4096 fp32
    float* sMR   = sm + 4096;                // 64*SSTR tf32 bits
    float* sXs0  = sMR + 64 * SSTR;          // slot 0 tile (T in-place); slot 1 follows

    int warp = tid >> 5, lane = tid & 31;
    int g = lane >> 2, t4 = lane & 3;
    int wslot = warp >> 2;                   // which of the 2 tiles
    int strip = (warp & 3) * 16;             // 16 output rows within tile
    int slot  = tid >> 7;                    // staging slot (== wslot)
    int t128  = tid & 127;
    float* sXw  = sXs0 + wslot * 64 * SSTR;  // this warp's tile buffer
    float* sXst = sXs0 + slot * 64 * SSTR;   // staging target

    for (int i = tid; i < 4096; i += 256) {
        sDiag[i] = diag_scale[i];
        int r = i >> 6, c = i & 63;
        sMR[r * SSTR + c] = __uint_as_float(f2tf(g_MR[i]));
    }
    unsigned a1f[8][4];
#pragma unroll
    for (int kk = 0; kk < 8; ++kk) {
        int i0 = kk * 8 + t4;
        a1f[kk][0] = f2tf(g_ML[(strip + g)     * 64 + i0]);
        a1f[kk][1] = f2tf(g_ML[(strip + g + 8) * 64 + i0]);
        a1f[kk][2] = f2tf(g_ML[(strip + g)     * 64 + i0 + 4]);
        a1f[kk][3] = f2tf(g_ML[(strip + g + 8) * 64 + i0 + 4]);
    }
    if (tid == 0) sp = atomicAdd(&g_work, 1u);   // leader grabs first pair
    __syncthreads();                              // init done + sp visible

    int npairs = (ntiles + 1) >> 1;
    unsigned p = sp;                              // block-uniform
    float4 pf[8];
    {
        int tile = 2 * (int)p + slot;
        if ((int)p < npairs && tile < ntiles) {
            const float4* xt = (const float4*)(x + (size_t)tile * 4096);
#pragma unroll
            for (int it = 0; it < 8; ++it) pf[it] = xt[it * 128 + t128];
        }
    }

    const float4* dg = (const float4*)sDiag;
    while ((int)p < npairs) {
        int tile = 2 * (int)p + slot;
        // ---- stage Xs (tf32) for this slot ----
        if (tile < ntiles) {
#pragma unroll
            for (int it = 0; it < 8; ++it) {
                int idx = it * 128 + t128;
                float4 v = pf[it];
                float4 s = dg[idx];
                uint4 pk = make_uint4(f2tf(v.x * s.x), f2tf(v.y * s.y),
                                      f2tf(v.z * s.z), f2tf(v.w * s.w));
                int row = idx >> 4, col = (idx & 15) << 2;
                *(uint4*)&sXst[row * SSTR + col] = pk;
            }
        }
        if (tid == 0) sp = atomicAdd(&g_work, 1u);  // leader grabs next pair
        __syncthreads();                            // staging done + sp visible
        unsigned pn = sp;                           // block-uniform next pair

        // ---- issue next pair's loads early (overlap with GEMMs) ----
        {
            int tn = 2 * (int)pn + slot;
            if ((int)pn < npairs && tn < ntiles) {
                const float4* xt = (const float4*)(x + (size_t)tn * 4096);
#pragma unroll
                for (int it = 0; it < 8; ++it) pf[it] = xt[it * 128 + t128];
            }
        }

        // ---- GEMM1: T_strip = (M_L^T)_strip @ Xs (regs) ----
        float c1[8][4];
#pragma unroll
        for (int nn = 0; nn < 8; ++nn) {
            c1[nn][0] = 0.f; c1[nn][1] = 0.f; c1[nn][2] = 0.f; c1[nn][3] = 0.f;
#pragma unroll
            for (int kk = 0; kk < 8; ++kk) {
                unsigned b0 = __float_as_uint(sXw[(kk * 8 + t4)     * SSTR + nn * 8 + g]);
                unsigned b1 = __float_as_uint(sXw[(kk * 8 + t4 + 4) * SSTR + nn * 8 + g]);
                mma_tf32(c1[nn][0], c1[nn][1], c1[nn][2], c1[nn][3],
                         a1f[kk][0], a1f[kk][1], a1f[kk][2], a1f[kk][3], b0, b1);
            }
        }
        __syncthreads();   // all reads of Xs done -> overwrite with T

        // ---- write T strip in-place ----
#pragma unroll
        for (int nn = 0; nn < 8; ++nn) {
            *(uint2*)&sXw[(strip + g)     * SSTR + nn * 8 + 2 * t4] =
                make_uint2(f2tf(c1[nn][0]), f2tf(c1[nn][1]));
            *(uint2*)&sXw[(strip + g + 8) * SSTR + nn * 8 + 2 * t4] =
                make_uint2(f2tf(c1[nn][2]), f2tf(c1[nn][3]));
        }
        __syncwarp();   // strip is warp-private

        unsigned a2f[8][4];
#pragma unroll
        for (int kk = 0; kk < 8; ++kk) {
            int j0 = kk * 8 + t4;
            a2f[kk][0] = __float_as_uint(sXw[(strip + g)     * SSTR + j0]);
            a2f[kk][1] = __float_as_uint(sXw[(strip + g + 8) * SSTR + j0]);
            a2f[kk][2] = __float_as_uint(sXw[(strip + g)     * SSTR + j0 + 4]);
            a2f[kk][3] = __float_as_uint(sXw[(strip + g + 8) * SSTR + j0 + 4]);
        }

        // ---- GEMM2: O_strip = T_strip @ M_R ----
        int wtile = 2 * (int)p + wslot;
        if (wtile < ntiles) {
            float* ot = out + (size_t)wtile * 4096;
#pragma unroll
            for (int nn = 0; nn < 8; ++nn) {
                float c0 = 0.f, c1v = 0.f, c2 = 0.f, c3 = 0.f;
#pragma unroll
                for (int kk = 0; kk < 8; ++kk) {
                    unsigned b0 = __float_as_uint(sMR[(kk * 8 + t4)     * SSTR + nn * 8 + g]);
                    unsigned b1 = __float_as_uint(sMR[(kk * 8 + t4 + 4) * SSTR + nn * 8 + g]);
                    mma_tf32(c0, c1v, c2, c3,
                             a2f[kk][0], a2f[kk][1], a2f[kk][2], a2f[kk][3], b0, b1);
                }
                int row = strip + g, col = nn * 8 + 2 * t4;
                *(float2*)&ot[row * 64 + col]       = make_float2(c0, c1v);
                *(float2*)&ot[(row + 8) * 64 + col] = make_float2(c2, c3);
            }
        }
        __syncthreads();   // T consumed; sp reads done -> next iter may rewrite
        p = pn;
    }
}

// ---------------- launch ----------------
extern "C" void kernel_launch(void* const* d_in, const int* in_sizes, int n_in,
                              void* d_out, int out_size) {
    const float* x          = (const float*)d_in[0];
    const float* u_left     = (const float*)d_in[1];
    const float* v_left     = (const float*)d_in[2];
    const float* diag_left  = (const float*)d_in[3];
    const float* u_right    = (const float*)d_in[4];
    const float* v_right    = (const float*)d_in[5];
    const float* diag_right = (const float*)d_in[6];
    const float* diag_scale = (const float*)d_in[7];
    float* out = (float*)d_out;

    int ntiles = in_sizes[0] / 4096;

    // smem: max(prep: 4*64*68, kron: 4096 + 3*64*72) floats = 17920 fl = 71680 B
    const int SMEM_BYTES = (4096 + 3 * 64 * SSTR) * (int)sizeof(float);
    cudaFuncSetAttribute(fused_kernel, cudaFuncAttributeMaxDynamicSharedMemorySize, SMEM_BYTES);

    reset_kernel<<<1, 1>>>();
    fused_kernel<<<NBLK, 256, SMEM_BYTES>>>(x, u_left, v_left, diag_left,
                                            u_right, v_right, diag_right,
                                            diag_scale, out, ntiles);
}